// round 5
// baseline (speedup 1.0000x reference)
#include <cuda_runtime.h>
#include <cstddef>

#define C_DIM 64
#define K_DIM 64
#define P_DIM (256 * 256)        // H*W = 65536
#define RED_BLOCKS 256           // reduction blocks (256 pixels each)
#define N4_PER_REP (C_DIM * P_DIM / 4)   // 1,048,576 float4 per replica
#define CHUNKS_PER_REP 1024
#define F4_PER_CHUNK (N4_PER_REP / CHUNKS_PER_REP)  // 1024 float4 = 16KB

// Transposed partials: g_partial[i][r] so means reads contiguous r.
// Written unconditionally each launch -> no zeroing needed.
__device__ float g_partial[K_DIM * C_DIM][RED_BLOCKS];   // 4 MB
__device__ float g_pcnt[K_DIM][RED_BLOCKS];              // 64 KB

// ---------------------------------------------------------------------------
// Reduction: 256 blocks x 256 pixels. Label via one-hot scan, smem-atomic
// accumulate into padded [64][65] tile, flush to transposed partials.
// Runs concurrently with (and hides under) the DRAM-bound broadcast.
// ---------------------------------------------------------------------------
__global__ __launch_bounds__(256) void reduce_kernel(
    const float* __restrict__ x, const float* __restrict__ oh)
{
    __shared__ float ssum[K_DIM][C_DIM + 1];
    __shared__ float scnt[K_DIM];

    int bid = blockIdx.x;
    int tid = threadIdx.x;

    for (int i = tid; i < K_DIM * (C_DIM + 1); i += 256)
        (&ssum[0][0])[i] = 0.0f;
    if (tid < K_DIM) scnt[tid] = 0.0f;
    __syncthreads();

    int p = bid * 256 + tid;

    int label = 0;
    #pragma unroll 8
    for (int k = 0; k < K_DIM; k++) {
        if (__ldg(&oh[(size_t)k * P_DIM + p]) != 0.0f) label = k;
    }
    atomicAdd(&scnt[label], 1.0f);

    #pragma unroll 8
    for (int c = 0; c < C_DIM; c++) {
        atomicAdd(&ssum[label][c], __ldg(&x[(size_t)c * P_DIM + p]));
    }
    __syncthreads();

    for (int i = tid; i < K_DIM * C_DIM; i += 256) {
        g_partial[i][bid] = ssum[i >> 6][i & 63];
    }
    if (tid < K_DIM) g_pcnt[tid][bid] = scnt[tid];
}

// ---------------------------------------------------------------------------
// Means: one warp per (k,c). Lanes read 2 contiguous float4 (coalesced,
// L2-resident), butterfly-reduce. 512 blocks x 256 threads = 4096 warps.
// ---------------------------------------------------------------------------
__global__ __launch_bounds__(256) void means_kernel(float* __restrict__ out_means)
{
    int warp_g = (blockIdx.x * 256 + threadIdx.x) >> 5;   // 0..4095
    int lane   = threadIdx.x & 31;
    int k      = warp_g >> 6;

    const float4* prow = (const float4*)&g_partial[warp_g][0];  // 64 float4
    const float4* crow = (const float4*)&g_pcnt[k][0];          // 64 float4

    float4 a  = __ldg(prow + lane);
    float4 b  = __ldg(prow + 32 + lane);
    float4 ca = __ldg(crow + lane);
    float4 cb = __ldg(crow + 32 + lane);

    float s   = (a.x + a.y) + (a.z + a.w) + (b.x + b.y) + (b.z + b.w);
    float cnt = (ca.x + ca.y) + (ca.z + ca.w) + (cb.x + cb.y) + (cb.z + cb.w);

    #pragma unroll
    for (int off = 16; off > 0; off >>= 1) {
        s   += __shfl_xor_sync(0xFFFFFFFFu, s, off);
        cnt += __shfl_xor_sync(0xFFFFFFFFu, cnt, off);
    }

    if (lane == 0) {
        float denom = cnt + (cnt == 0.0f ? 1.0f : 0.0f);
        out_means[warp_g] = s / denom;
    }
}

// ---------------------------------------------------------------------------
// Broadcast: one 16 KB chunk of one replica per block (proven R4 pattern).
// Streaming stores keep x L2-resident; DRAM-write-bound at ~81% of spec.
// ---------------------------------------------------------------------------
__global__ __launch_bounds__(256) void broadcast_kernel(
    const float* __restrict__ x, float4* __restrict__ out4)
{
    int b   = blockIdx.x;
    int k   = b >> 10;                   // replica index
    int cb  = b & (CHUNKS_PER_REP - 1);
    int tid = threadIdx.x;

    const float4* src = (const float4*)x + (size_t)cb * F4_PER_CHUNK;
    float4* dst = out4 + (size_t)k * N4_PER_REP + (size_t)cb * F4_PER_CHUNK;

    float4 v0 = __ldg(src + tid);
    float4 v1 = __ldg(src + 256 + tid);
    float4 v2 = __ldg(src + 512 + tid);
    float4 v3 = __ldg(src + 768 + tid);
    __stcs(dst + tid,       v0);
    __stcs(dst + 256 + tid, v1);
    __stcs(dst + 512 + tid, v2);
    __stcs(dst + 768 + tid, v3);
}

// ---------------------------------------------------------------------------
// Launch topology: fork a side stream so (reduce -> means) runs concurrently
// with the broadcast; the ~10us side chain hides under the ~164us copy.
// Stream/events are created ONCE on the first (non-captured) correctness call.
// ---------------------------------------------------------------------------
extern "C" void kernel_launch(void* const* d_in, const int* in_sizes, int n_in,
                              void* d_out, int out_size)
{
    const float* x  = (const float*)d_in[0];   // [1, 64, 256, 256]
    const float* oh = (const float*)d_in[1];   // [1, 64, 256, 256] one-hot
    float* out = (float*)d_out;

    float* out_means = out + (size_t)out_size - (size_t)(K_DIM * C_DIM);

    static cudaStream_t side = nullptr;
    static cudaEvent_t e_fork = nullptr, e_join = nullptr;
    if (side == nullptr) {
        cudaStreamCreateWithFlags(&side, cudaStreamNonBlocking);
        cudaEventCreateWithFlags(&e_fork, cudaEventDisableTiming);
        cudaEventCreateWithFlags(&e_join, cudaEventDisableTiming);
    }

    cudaStream_t main_s = 0;  // capturing / default stream

    // Fork: side stream branches off the capturing stream.
    cudaEventRecord(e_fork, main_s);
    cudaStreamWaitEvent(side, e_fork, 0);

    // Side chain: reduction -> means (completes ~10us in).
    reduce_kernel<<<RED_BLOCKS, 256, 0, side>>>(x, oh);
    means_kernel<<<512, 256, 0, side>>>(out_means);
    cudaEventRecord(e_join, side);

    // Main: the 1 GiB broadcast (critical path).
    broadcast_kernel<<<K_DIM * CHUNKS_PER_REP, 256, 0, main_s>>>(x, (float4*)out);

    // Join: graph completes when both branches are done.
    cudaStreamWaitEvent(main_s, e_join, 0);
}